// round 12
// baseline (speedup 1.0000x reference)
#include <cuda_runtime.h>
#include <cuda_bf16.h>
#include <cstdint>

#define BB 16
#define NNODE 512
#define MNB 16
#define HH 8
#define DD 128
#define BN 8192
#define HD 1024
#define FFD 256

// ---------------- scratch globals ----------------
__device__ float g_Wh[(size_t)BN * HD];
__device__ float g_ssrc[(size_t)BN * HH];
__device__ float g_sdst[(size_t)BN * HH];
__device__ float g_agg[(size_t)BN * HD];
__device__ float g_t[(size_t)BN * DD];
__device__ float g_u[(size_t)BN * FFD];
__device__ float g_part[(size_t)4 * BN * DD];       // split-K partials

__device__ __nv_bfloat16 g_Wt_hi[(size_t)HH * DD * DD];  // [h][e][d]
__device__ __nv_bfloat16 g_Wt_lo[(size_t)HH * DD * DD];
__device__ __nv_bfloat16 g_Wot_hi[(size_t)DD * HD];      // [n][k]
__device__ __nv_bfloat16 g_Wot_lo[(size_t)DD * HD];
__device__ __nv_bfloat16 g_w1t_hi[(size_t)FFD * DD];
__device__ __nv_bfloat16 g_w1t_lo[(size_t)FFD * DD];
__device__ __nv_bfloat16 g_w2t_hi[(size_t)DD * FFD];
__device__ __nv_bfloat16 g_w2t_lo[(size_t)DD * FFD];

// ---------------- smem layout (M-tile = 64 -> 2 CTAs/SM) ----------------
#define APITCH 136
#define MT 64
#define A_TILE_BYTES (MT * APITCH * 2)      // 17408
#define B_TILE_BYTES (128 * APITCH * 2)     // 34816
#define OFF_AH 2048
#define OFF_AL (OFF_AH + A_TILE_BYTES)
#define OFF_BH (OFF_AL + A_TILE_BYTES)
#define OFF_BL (OFF_BH + B_TILE_BYTES)
#define GEMM_SMEM (OFF_BL + B_TILE_BYTES)   // 106496
#define SPITCH 132

__device__ __forceinline__ void mma16816(float* d, const uint32_t* a,
                                         uint32_t b0, uint32_t b1) {
    asm volatile(
        "mma.sync.aligned.m16n8k16.row.col.f32.bf16.bf16.f32 "
        "{%0,%1,%2,%3}, {%4,%5,%6,%7}, {%8,%9}, {%0,%1,%2,%3};"
        : "+f"(d[0]), "+f"(d[1]), "+f"(d[2]), "+f"(d[3])
        : "r"(a[0]), "r"(a[1]), "r"(a[2]), "r"(a[3]), "r"(b0), "r"(b1));
}
__device__ __forceinline__ void ldsm_x4(uint32_t* r, uint32_t addr) {
    asm volatile(
        "ldmatrix.sync.aligned.m8n8.x4.shared.b16 {%0,%1,%2,%3}, [%4];"
        : "=r"(r[0]), "=r"(r[1]), "=r"(r[2]), "=r"(r[3]) : "r"(addr));
}
__device__ __forceinline__ void cp_async16(uint32_t saddr, const void* gaddr) {
    asm volatile("cp.async.cg.shared.global [%0], [%1], 16;"
                 :: "r"(saddr), "l"(gaddr));
}
__device__ __forceinline__ void cp_async_wait_all() {
    asm volatile("cp.async.commit_group;");
    asm volatile("cp.async.wait_group 0;");
}
__device__ __forceinline__ void split4(float4 v, uint2& hi, uint2& lo) {
    __nv_bfloat162 h0 = __floats2bfloat162_rn(v.x, v.y);
    __nv_bfloat162 h1 = __floats2bfloat162_rn(v.z, v.w);
    __nv_bfloat162 l0 = __floats2bfloat162_rn(v.x - __bfloat162float(h0.x),
                                              v.y - __bfloat162float(h0.y));
    __nv_bfloat162 l1 = __floats2bfloat162_rn(v.z - __bfloat162float(h1.x),
                                              v.w - __bfloat162float(h1.y));
    hi = make_uint2(*(uint32_t*)&h0, *(uint32_t*)&h1);
    lo = make_uint2(*(uint32_t*)&l0, *(uint32_t*)&l1);
}
__device__ __forceinline__ float warp_sum(float v) {
#pragma unroll
    for (int o = 16; o > 0; o >>= 1) v += __shfl_xor_sync(0xffffffffu, v, o);
    return v;
}

// ---------------- prep: transpose + bf16-split weights ----------------
__global__ void __launch_bounds__(256) prep_weights(
    const float* __restrict__ W, const float* __restrict__ Wo,
    const float* __restrict__ w1, const float* __restrict__ w2)
{
    int i = blockIdx.x * 256 + threadIdx.x;
    float v; size_t dst; __nv_bfloat16 *ph, *pl;
    if (i < 131072) {
        int h = i >> 14, d = (i >> 7) & 127, e = i & 127;
        v = W[i]; dst = (size_t)h * 16384 + (size_t)e * 128 + d;
        ph = g_Wt_hi; pl = g_Wt_lo;
    } else if (i < 262144) {
        int j = i - 131072; int k = j >> 7, n = j & 127;
        v = Wo[j]; dst = (size_t)n * 1024 + k;
        ph = g_Wot_hi; pl = g_Wot_lo;
    } else if (i < 294912) {
        int j = i - 262144; int k = j >> 8, n = j & 255;
        v = w1[j]; dst = (size_t)n * 128 + k;
        ph = g_w1t_hi; pl = g_w1t_lo;
    } else if (i < 327680) {
        int j = i - 294912; int k = j >> 7, n = j & 127;
        v = w2[j]; dst = (size_t)n * 256 + k;
        ph = g_w2t_hi; pl = g_w2t_lo;
    } else return;
    __nv_bfloat16 hb = __float2bfloat16(v);
    ph[dst] = hb;
    pl[dst] = __float2bfloat16(v - __bfloat162float(hb));
}

// ---------------- HMMA GEMM (64x128 tile, ldmatrix + cp.async B) ----------------
// MODE 0: Wh = h @ W[head], + ssrc/sdst        grid(128, 8)
// MODE 1: part = agg @ Wo  (split-K 4)         grid(128, 4), raw partials
// MODE 2: u = relu(t @ w1 + b1)                grid(128, 2)
// MODE 3: part = u @ w2   (split-K 2)          grid(128, 2), raw partials
template <int MODE>
__global__ void __launch_bounds__(256, 2) gemm_mma(
    const float* __restrict__ Aext, const float* __restrict__ p0,
    const float* __restrict__ p1)
{
    extern __shared__ char sm[];
    const int tid = threadIdx.x;
    const int warp = tid >> 5;
    const int lane = tid & 31;
    const int n0 = blockIdx.x * MT;
    const int by = blockIdx.y;
    const int wm = (warp & 1) * 32;      // 2 warps over M=64
    const int wn = (warp >> 1) * 32;     // 4 warps over N=128
    const int rr = lane >> 2;
    const int cc = (lane & 3) * 2;
    const int lrow = lane & 15;          // ldmatrix address row-within-16
    const int lcol = (lane >> 4) * 8;    // ldmatrix address col select

    constexpr int LDA = (MODE == 0) ? 128 : (MODE == 1) ? 1024 : (MODE == 2) ? 128 : 256;
    constexpr int LDB = LDA;
    constexpr int KP  = (MODE == 1) ? 2 : 1;
    constexpr bool SPLIT = (MODE == 1 || MODE == 3);
    constexpr int LDOUT = (MODE == 0) ? 1024 : (MODE == 2) ? 256 : 128;

    const int kbase = (MODE == 1) ? by * 256 : (MODE == 3) ? by * 128 : 0;

    const float* A = (MODE == 0) ? Aext : (MODE == 1) ? g_agg : (MODE == 2) ? g_t : g_u;
    const __nv_bfloat16 *Bh, *Bl;
    int coff = 0;
    if (MODE == 0) { Bh = g_Wt_hi + (size_t)by * 16384; Bl = g_Wt_lo + (size_t)by * 16384; coff = by * 128; }
    if (MODE == 1) { Bh = g_Wot_hi; Bl = g_Wot_lo; }
    if (MODE == 2) { Bh = g_w1t_hi + (size_t)by * 16384; Bl = g_w1t_lo + (size_t)by * 16384; coff = by * 128; }
    if (MODE == 3) { Bh = g_w2t_hi; Bl = g_w2t_lo; }
    float* outbase = (MODE == 0) ? g_Wh : (MODE == 2) ? g_u
                                        : (g_part + (size_t)by * BN * DD);

    __nv_bfloat16* Ah_s = (__nv_bfloat16*)(sm + OFF_AH);
    __nv_bfloat16* Al_s = (__nv_bfloat16*)(sm + OFF_AL);
    float* s_v0 = (float*)(sm + 64);
    float* s_v1 = (float*)(sm + 576);
    float* sst  = (float*)(sm + OFF_AH);   // fp32 staging, reuses tiles

    const uint32_t smem_u32 = (uint32_t)__cvta_generic_to_shared(sm);
    const uint32_t ah_b = smem_u32 + OFF_AH;
    const uint32_t al_b = smem_u32 + OFF_AL;
    const uint32_t bh_b = smem_u32 + OFF_BH;
    const uint32_t bl_b = smem_u32 + OFF_BL;

    if (tid < 128 && !SPLIT) {
        if (MODE == 0) { s_v0[tid] = p0[by * 128 + tid]; s_v1[tid] = p1[by * 128 + tid]; }
        if (MODE == 2) { s_v0[tid] = p0[by * 128 + tid]; }
    }

    float d[2][4][4];
#pragma unroll
    for (int mi = 0; mi < 2; mi++)
#pragma unroll
        for (int ni = 0; ni < 4; ni++)
#pragma unroll
            for (int j = 0; j < 4; j++) d[mi][ni][j] = 0.f;

    for (int kp = 0; kp < KP; kp++) {
        const int kb0 = kbase + kp * 128;
        // B tile: async global->smem (pre-split bf16, no register round-trip)
#pragma unroll
        for (int t = 0; t < 8; t++) {
            int f8 = t * 256 + tid;
            int n = f8 >> 4, g = f8 & 15;
            uint32_t soff = (uint32_t)(n * APITCH + g * 8) * 2;
            cp_async16(bh_b + soff, Bh + (size_t)n * LDB + kb0 + g * 8);
            cp_async16(bl_b + soff, Bl + (size_t)n * LDB + kb0 + g * 8);
        }
        // A tile: fp32 load + convert (overlaps with in-flight B cp.async)
#pragma unroll
        for (int t = 0; t < 8; t++) {
            int f4 = t * 256 + tid;
            int row = f4 >> 5, q = f4 & 31;
            float4 v = *(const float4*)(A + (size_t)(n0 + row) * LDA + kb0 + q * 4);
            uint2 hi, lo; split4(v, hi, lo);
            size_t off = ((size_t)row * APITCH + q * 4) * 2;
            *(uint2*)((char*)Ah_s + off) = hi;
            *(uint2*)((char*)Al_s + off) = lo;
        }
        cp_async_wait_all();
        __syncthreads();

#pragma unroll
        for (int ks = 0; ks < 8; ks++) {
            const int ck = ks * 16;
            // A frags: 2 ldmatrix.x4 per hi/lo (16x16 each)
            uint32_t ah[2][4], al[2][4];
#pragma unroll
            for (int mi = 0; mi < 2; mi++) {
                uint32_t aoff = (uint32_t)((wm + mi * 16 + lrow) * APITCH + ck + lcol) * 2;
                ldsm_x4(ah[mi], ah_b + aoff);
                ldsm_x4(al[mi], al_b + aoff);
            }
            // B frags: x4 at n-bases wn, wn+16 covers ni pairs {0,1},{2,3}
            //   r0 = b0(ni even), r1 = b0(ni odd), r2 = b1(ni even), r3 = b1(ni odd)
            uint32_t bhf[2][4], blf[2][4];
#pragma unroll
            for (int p = 0; p < 2; p++) {
                uint32_t boff = (uint32_t)((wn + p * 16 + lrow) * APITCH + ck + lcol) * 2;
                ldsm_x4(bhf[p], bh_b + boff);
                ldsm_x4(blf[p], bl_b + boff);
            }
#pragma unroll
            for (int mi = 0; mi < 2; mi++)
#pragma unroll
                for (int ni = 0; ni < 4; ni++) {
                    const int p = ni >> 1, o = ni & 1;
                    uint32_t b0h = bhf[p][o],     b1h = bhf[p][o + 2];
                    uint32_t b0l = blf[p][o],     b1l = blf[p][o + 2];
                    mma16816(d[mi][ni], ah[mi], b0h, b1h);
                    mma16816(d[mi][ni], ah[mi], b0l, b1l);
                    mma16816(d[mi][ni], al[mi], b0h, b1h);
                }
        }
        __syncthreads();
    }

    // stage D -> smem
#pragma unroll
    for (int mi = 0; mi < 2; mi++)
#pragma unroll
        for (int ni = 0; ni < 4; ni++) {
            int r = wm + mi * 16 + rr, c = wn + ni * 8 + cc;
            *(float2*)(sst + (size_t)r * SPITCH + c)       = make_float2(d[mi][ni][0], d[mi][ni][1]);
            *(float2*)(sst + (size_t)(r + 8) * SPITCH + c) = make_float2(d[mi][ni][2], d[mi][ni][3]);
        }
    __syncthreads();

    if (tid < MT && !SPLIT) {
        float4* row4 = (float4*)(sst + (size_t)tid * SPITCH);
        const int grow = n0 + tid;
        if (MODE == 0) {
            float ps = 0.f, pd = 0.f;
            const float4* sv0 = (const float4*)s_v0;
            const float4* sv1 = (const float4*)s_v1;
#pragma unroll
            for (int q = 0; q < 32; q++) {
                float4 v = row4[q], a = sv0[q], b = sv1[q];
                ps += v.x * a.x + v.y * a.y + v.z * a.z + v.w * a.w;
                pd += v.x * b.x + v.y * b.y + v.z * b.z + v.w * b.w;
            }
            g_ssrc[(size_t)grow * HH + by] = ps;
            g_sdst[(size_t)grow * HH + by] = pd;
        } else if (MODE == 2) {
            const float4* bv = (const float4*)s_v0;
#pragma unroll
            for (int q = 0; q < 32; q++) {
                float4 v = row4[q], b = bv[q];
                v.x = fmaxf(v.x + b.x, 0.f); v.y = fmaxf(v.y + b.y, 0.f);
                v.z = fmaxf(v.z + b.z, 0.f); v.w = fmaxf(v.w + b.w, 0.f);
                row4[q] = v;
            }
        }
    }
    __syncthreads();

    for (int idx = tid; idx < MT * 32; idx += 256) {
        int rr2 = idx >> 5, q = idx & 31;
        float4 v = *(const float4*)(sst + (size_t)rr2 * SPITCH + q * 4);
        *(float4*)(outbase + (size_t)(n0 + rr2) * LDOUT + coff + q * 4) = v;
    }
}

// ---------------- split-K reduce + residual (+bias) + LayerNorm ----------------
// RES_EXT / OUT_EXT select harness pointers vs device globals referenced
// directly in device code. NEVER pass __device__ globals as kernel args from
// host (host shadow address + GB300 ATS = silent writes to host memory).
template <int NP, bool BIAS, bool RES_EXT, bool OUT_EXT>
__global__ void __launch_bounds__(256) ln_reduce(
    const float* __restrict__ res, const float* __restrict__ bias,
    const float* __restrict__ gam, const float* __restrict__ bet,
    float* __restrict__ outp)
{
    const int row = blockIdx.x * 8 + (threadIdx.x >> 5);
    const int lane = threadIdx.x & 31;
    const float* resp = RES_EXT ? (res + (size_t)row * 128) : (g_t + (size_t)row * 128);
    float* outrow = OUT_EXT ? (outp + (size_t)row * 128 + lane * 4)
                            : (g_t + (size_t)row * 128 + lane * 4);

    float4 acc = *(const float4*)(resp + lane * 4);
#pragma unroll
    for (int p = 0; p < NP; p++) {
        float4 v = *(const float4*)(g_part + (size_t)p * BN * DD + (size_t)row * 128 + lane * 4);
        acc.x += v.x; acc.y += v.y; acc.z += v.z; acc.w += v.w;
    }
    if (BIAS) {
        float4 b = *(const float4*)(bias + lane * 4);
        acc.x += b.x; acc.y += b.y; acc.z += b.z; acc.w += b.w;
    }
    const float mu = warp_sum(acc.x + acc.y + acc.z + acc.w) * (1.f / 128.f);
    float x0 = acc.x - mu, x1 = acc.y - mu, x2 = acc.z - mu, x3 = acc.w - mu;
    const float var = warp_sum(x0 * x0 + x1 * x1 + x2 * x2 + x3 * x3) * (1.f / 128.f);
    const float rs = rsqrtf(var + 1e-5f);
    float4 g = *(const float4*)(gam + lane * 4);
    float4 b = *(const float4*)(bet + lane * 4);
    float4 y;
    y.x = x0 * rs * g.x + b.x; y.y = x1 * rs * g.y + b.y;
    y.z = x2 * rs * g.z + b.z; y.w = x3 * rs * g.w + b.w;
    *(float4*)outrow = y;
}

// ---------------- K2: attention softmax + L2 gather aggregation ----------------
__global__ void __launch_bounds__(256) k2_attn(
    const int* __restrict__ adj, const int* __restrict__ nlist)
{
    const int node = blockIdx.x;
    const int b = node >> 9;
    const int tx = threadIdx.x;

    __shared__ int   nls[MNB];
    __shared__ int   adjs[MNB];
    __shared__ float es[MNB][HH];
    __shared__ float attn_s[MNB][HH];

    if (tx < MNB) {
        nls[tx]  = nlist[(size_t)node * MNB + tx];
        adjs[tx] = adj[(size_t)node * MNB + tx];
    }
    __syncthreads();

    if (tx < MNB * HH) {
        const int m = tx >> 3, hh = tx & 7;
        float v = g_ssrc[(size_t)node * HH + hh]
                + g_sdst[(size_t)((b << 9) + nls[m]) * HH + hh];
        v = v > 0.f ? v : 0.2f * v;
        if (adjs[m] <= 0) v = -1e9f;
        es[m][hh] = v;
    }
    __syncthreads();

    if (tx < HH) {
        float mx = -3.4e38f;
#pragma unroll
        for (int m = 0; m < MNB; m++) mx = fmaxf(mx, es[m][tx]);
        float ex[MNB], s = 0.f;
#pragma unroll
        for (int m = 0; m < MNB; m++) { ex[m] = expf(es[m][tx] - mx); s += ex[m]; }
        const float inv = 1.f / s;
#pragma unroll
        for (int m = 0; m < MNB; m++) attn_s[m][tx] = ex[m] * inv;
    }
    __syncthreads();

    const int hh = tx >> 5;
    const float4* whb = (const float4*)g_Wh + (size_t)(b << 9) * 256;
    float4 acc = make_float4(0.f, 0.f, 0.f, 0.f);
#pragma unroll
    for (int m = 0; m < MNB; m++) {
        const float wgt = attn_s[m][hh];
        const float4 v = whb[(size_t)nls[m] * 256 + tx];
        acc.x = fmaf(wgt, v.x, acc.x);
        acc.y = fmaf(wgt, v.y, acc.y);
        acc.z = fmaf(wgt, v.z, acc.z);
        acc.w = fmaf(wgt, v.w, acc.w);
    }
    ((float4*)g_agg)[(size_t)node * 256 + tx] = acc;
}

// ---------------------------------------------------------------------------
extern "C" void kernel_launch(void* const* d_in, const int* in_sizes, int n_in,
                              void* d_out, int out_size)
{
    const float* h     = (const float*)d_in[0];
    const int*   adj   = (const int*)d_in[1];
    const int*   nlist = (const int*)d_in[2];
    const float* W     = (const float*)d_in[3];
    const float* a_src = (const float*)d_in[4];
    const float* a_dst = (const float*)d_in[5];
    const float* Wo    = (const float*)d_in[6];
    const float* ln1g  = (const float*)d_in[7];
    const float* ln1b  = (const float*)d_in[8];
    const float* w1    = (const float*)d_in[9];
    const float* b1    = (const float*)d_in[10];
    const float* w2    = (const float*)d_in[11];
    const float* b2    = (const float*)d_in[12];
    const float* ln2g  = (const float*)d_in[13];
    const float* ln2b  = (const float*)d_in[14];
    float* out = (float*)d_out;

    static bool attr_done = false;
    if (!attr_done) {
        cudaFuncSetAttribute(gemm_mma<0>, cudaFuncAttributeMaxDynamicSharedMemorySize, GEMM_SMEM);
        cudaFuncSetAttribute(gemm_mma<1>, cudaFuncAttributeMaxDynamicSharedMemorySize, GEMM_SMEM);
        cudaFuncSetAttribute(gemm_mma<2>, cudaFuncAttributeMaxDynamicSharedMemorySize, GEMM_SMEM);
        cudaFuncSetAttribute(gemm_mma<3>, cudaFuncAttributeMaxDynamicSharedMemorySize, GEMM_SMEM);
        attr_done = true;
    }

    prep_weights<<<1280, 256>>>(W, Wo, w1, w2);
    gemm_mma<0><<<dim3(128, 8), 256, GEMM_SMEM>>>(h, a_src, a_dst);
    k2_attn<<<BN, 256>>>(adj, nlist);
    gemm_mma<1><<<dim3(128, 4), 256, GEMM_SMEM>>>(nullptr, nullptr, nullptr);
    // LN1: res = h (ext), out -> g_t (internal)
    ln_reduce<4, false, true, false><<<1024, 256>>>(h, nullptr, ln1g, ln1b, nullptr);
    gemm_mma<2><<<dim3(128, 2), 256, GEMM_SMEM>>>(nullptr, b1, nullptr);
    gemm_mma<3><<<dim3(128, 2), 256, GEMM_SMEM>>>(nullptr, nullptr, nullptr);
    // LN2: res = g_t (internal), out -> d_out (ext)
    ln_reduce<2, true, false, true><<<1024, 256>>>(nullptr, b2, ln2g, ln2b, out);
}